// round 16
// baseline (speedup 1.0000x reference)
#include <cuda_runtime.h>
#include <cuda_fp16.h>
#include <mma.h>
#include <cstdint>

using namespace nvcuda;

// Problem constants
#define BATCH  4
#define SEQ    4096
#define DMODEL 1024
#define NHEAD  16
#define HDIM   64
#define DFF    4096
#define WIN    512
#define MROWS  (BATCH*SEQ)          // 16384

// ---------------- scratch (device globals; no allocations allowed) ----------
static __device__ float g_attn[(size_t)MROWS * DMODEL];
static __device__ float g_xln [(size_t)MROWS * DMODEL];
static __device__ float g_y   [(size_t)MROWS * DMODEL];
// fp16 planes
static __device__ __align__(16) __half g_srch[(size_t)MROWS * DMODEL];
static __device__ __align__(16) __half g_wqkvh[(size_t)3 * DMODEL * DMODEL];
static __device__ __align__(16) __half g_w1h[(size_t)DFF * DMODEL];
static __device__ __align__(16) __half g_w2h[(size_t)DMODEL * DFF];
static __device__ __align__(16) __half g_xh [(size_t)MROWS * DMODEL];
static __device__ __align__(16) __half g_hh [(size_t)MROWS * DFF];
// q/k/v planes, [3][B,H,S,d]
static __device__ __align__(16) __half g_qkvh[(size_t)3 * MROWS * DMODEL];
static __device__ float g_bqkv[3 * DMODEL];

__device__ __forceinline__ void cp16(void* dst, const void* src) {
    unsigned int d = (unsigned int)__cvta_generic_to_shared(dst);
    asm volatile("cp.async.cg.shared.global [%0], [%1], 16;\n" :: "r"(d), "l"(src));
}
__device__ __forceinline__ void cp16s(unsigned dst, const void* src) {
    asm volatile("cp.async.cg.shared.global [%0], [%1], 16;\n" :: "r"(dst), "l"(src));
}

__device__ __forceinline__ void hi_store4(float4 x, __half* hp) {
    ((__half2*)hp)[0] = __floats2half2_rn(x.x, x.y);
    ((__half2*)hp)[1] = __floats2half2_rn(x.z, x.w);
}

__device__ __forceinline__ void ldsm4(unsigned* r, unsigned a) {
    asm volatile("ldmatrix.sync.aligned.m8n8.x4.shared.b16 {%0,%1,%2,%3}, [%4];"
                 : "=r"(r[0]), "=r"(r[1]), "=r"(r[2]), "=r"(r[3]) : "r"(a));
}
__device__ __forceinline__ void ldsm4t(unsigned* r, unsigned a) {
    asm volatile("ldmatrix.sync.aligned.m8n8.x4.trans.shared.b16 {%0,%1,%2,%3}, [%4];"
                 : "=r"(r[0]), "=r"(r[1]), "=r"(r[2]), "=r"(r[3]) : "r"(a));
}
__device__ __forceinline__ void mma16816(float* c, const unsigned* a, const unsigned* b) {
    asm volatile("mma.sync.aligned.m16n8k16.row.col.f32.f16.f16.f32 "
                 "{%0,%1,%2,%3}, {%4,%5,%6,%7}, {%8,%9}, {%0,%1,%2,%3};"
                 : "+f"(c[0]), "+f"(c[1]), "+f"(c[2]), "+f"(c[3])
                 : "r"(a[0]), "r"(a[1]), "r"(a[2]), "r"(a[3]), "r"(b[0]), "r"(b[1]));
}

// ============================================================================
// Fused prepass: src + weights -> fp16; bias pack fp32. float4-group indices.
// ============================================================================
#define RA_TOTAL 7078656
__global__ __launch_bounds__(256)
void round_all(const float* __restrict__ src,
               const float* __restrict__ wq, const float* __restrict__ wk,
               const float* __restrict__ wv, const float* __restrict__ w1,
               const float* __restrict__ w2, const float* __restrict__ bq,
               const float* __restrict__ bk, const float* __restrict__ bv,
               __half* __restrict__ srch, __half* __restrict__ wqkvh,
               __half* __restrict__ w1h, __half* __restrict__ w2h,
               float* __restrict__ bqkv)
{
    long long i = (long long)blockIdx.x * 256 + threadIdx.x;
    if (i >= RA_TOTAL) return;
    if (i >= 7077888) {                 // bias pack, fp32 copy
        long long j = i - 7077888;      // 0..767
        const float* in;
        float* op;
        if (j < 256)      { in = bq + j * 4;         op = bqkv + j * 4; }
        else if (j < 512) { in = bk + (j - 256) * 4; op = bqkv + 1024 + (j - 256) * 4; }
        else              { in = bv + (j - 512) * 4; op = bqkv + 2048 + (j - 512) * 4; }
        *(float4*)op = *(const float4*)in;
        return;
    }
    const float* in;
    __half* hp;
    if (i < 4194304)      { in = src + i * 4; hp = srch + i * 4; }
    else if (i < 4456448) { long long j = i - 4194304; in = wq + j * 4; hp = wqkvh + j * 4; }
    else if (i < 4718592) { long long j = i - 4456448; in = wk + j * 4; hp = wqkvh + 1048576 + j * 4; }
    else if (i < 4980736) { long long j = i - 4718592; in = wv + j * 4; hp = wqkvh + 2097152 + j * 4; }
    else if (i < 6029312) { long long j = i - 4980736; in = w1 + j * 4; hp = w1h + j * 4; }
    else                  { long long j = i - 6029312; in = w2 + j * 4; hp = w2h + j * 4; }
    hi_store4(*(const float4*)in, hp);
}

// ============================================================================
// Plain-fp16 TN GEMM, 3-stage cp.async pipeline (wait_group 1):
// loads get ~2 compute iterations of slack vs DRAM latency.
// Block 128x128, BK=32, 8 warps as 4(m:32) x 2(n:64), warp tile 32x64.
//   MODE 0: +bias(packed), QKV scatter -> fp16 planes [3][B,H,S,d]
//   MODE 1: +bias, ReLU, fp16 out (FFN1)
//   MODE 2: +bias, +extra fp32 residual, fp32 out (FFN2)
// ============================================================================
#define BM 128
#define BN 128
#define BK 32
#define LDB 40
#define PLANE (128 * LDB)
#define STG (2 * PLANE)              // 10240 halfs = 20480 B per stage
#define NSTAGE 3
#define SPLIT_SMEM 69632             // max(3*STG*2=61440, epilogue 69632)
#define QKV_PLANE ((size_t)MROWS * DMODEL)

template <int MODE>
__global__ __launch_bounds__(256, 2)
void gemm_h(const __half* __restrict__ Ah, const __half* __restrict__ Wh,
            const float* __restrict__ bias, const float* __restrict__ extra,
            float* __restrict__ out0, __half* __restrict__ oh,
            int K, int N)
{
    extern __shared__ __half smp[];
    const int tid = threadIdx.x;
    const int wid = tid >> 5;
    const int lane = tid & 31;
    const int wm = wid & 3;
    const int wn = wid >> 2;

    wmma::fragment<wmma::accumulator, 16, 16, 16, float> acc[2][4];
#pragma unroll
    for (int i = 0; i < 2; i++)
#pragma unroll
        for (int j = 0; j < 4; j++)
            wmma::fill_fragment(acc[i][j], 0.0f);

    const __half* Ahg = Ah + (size_t)blockIdx.y * BM * K;
    const __half* Whg = Wh + (size_t)blockIdx.x * BN * K;

    auto load_stage = [&](int s, int kt) {
        __half* st = smp + s * STG;
#pragma unroll
        for (int p = 0; p < 2; p++) {
            int c = tid + p * 256;
            int r = c >> 2, col = (c & 3) * 8;
            size_t go = (size_t)r * K + kt + col;
            unsigned so = r * LDB + col;
            cp16(st + so,         Ahg + go);
            cp16(st + PLANE + so, Whg + go);
        }
        asm volatile("cp.async.commit_group;\n");
    };

    const int T = K / BK;
    load_stage(0, 0);
    load_stage(1, BK);

    int sidx = 0;                      // stage of tile t
    for (int t = 0; t < T; t++) {
        if (t + 2 < T)
            asm volatile("cp.async.wait_group 1;\n" ::: "memory");
        else
            asm volatile("cp.async.wait_group 0;\n" ::: "memory");
        __syncthreads();   // stage t visible; all warps done with stage t-1's buffer user
        if (t + 2 < T) {
            int s2 = sidx + 2; if (s2 >= NSTAGE) s2 -= NSTAGE;
            load_stage(s2, (t + 2) * BK);
        }

        const __half* Ahs = smp + sidx * STG;
        const __half* Bhs = Ahs + PLANE;

#pragma unroll
        for (int kk = 0; kk < BK; kk += 16) {
            wmma::fragment<wmma::matrix_a, 16, 16, 16, __half, wmma::row_major> ah[2];
#pragma unroll
            for (int i = 0; i < 2; i++)
                wmma::load_matrix_sync(ah[i], Ahs + (wm * 32 + i * 16) * LDB + kk, LDB);
#pragma unroll
            for (int j = 0; j < 4; j++) {
                wmma::fragment<wmma::matrix_b, 16, 16, 16, __half, wmma::col_major> bh;
                wmma::load_matrix_sync(bh, Bhs + (wn * 64 + j * 16) * LDB + kk, LDB);
#pragma unroll
                for (int i = 0; i < 2; i++)
                    wmma::mma_sync(acc[i][j], ah[i], bh, acc[i][j]);
            }
        }
        if (++sidx == NSTAGE) sidx = 0;
    }
    __syncthreads();   // all compute done before epilogue aliases stage smem

    float* Cw = (float*)smp + wid * (32 * 68);
#pragma unroll
    for (int i = 0; i < 2; i++)
#pragma unroll
        for (int j = 0; j < 4; j++)
            wmma::store_matrix_sync(Cw + (i * 16) * 68 + j * 16, acc[i][j], 68,
                                    wmma::mem_row_major);
    __syncwarp();

    const int m = blockIdx.y * BM + wm * 32 + lane;
    const int n0 = blockIdx.x * BN + wn * 64;
    const float* crow = Cw + lane * 68;

#pragma unroll
    for (int c4 = 0; c4 < 16; c4++) {
        int n = n0 + c4 * 4;
        float4 c = *(float4*)(crow + c4 * 4);
        float4 bb = *(const float4*)(bias + n);
        c.x += bb.x; c.y += bb.y; c.z += bb.z; c.w += bb.w;
        if constexpr (MODE == 1) {
            c.x = fmaxf(c.x, 0.f); c.y = fmaxf(c.y, 0.f);
            c.z = fmaxf(c.z, 0.f); c.w = fmaxf(c.w, 0.f);
            hi_store4(c, oh + (size_t)m * N + n);
        } else if constexpr (MODE == 2) {
            float4 e = *(const float4*)(extra + (size_t)m * N + n);
            c.x += e.x; c.y += e.y; c.z += e.z; c.w += e.w;
            *(float4*)(out0 + (size_t)m * N + n) = c;
        } else {
            int mat = n >> 10;
            int nl  = n & 1023;
            int h   = nl >> 6;
            int dd  = nl & (HDIM - 1);
            int bi  = m >> 12;
            int s   = m & (SEQ - 1);
            size_t o = (((size_t)bi * NHEAD + h) * SEQ + s) * HDIM + dd;
            hi_store4(c, oh + mat * QKV_PLANE + o);
        }
    }
}

// ============================================================================
// FlashAttention-2 style register-resident attention (unchanged from R15).
// ============================================================================
#define AQLD 72
#define APLANE (64 * AQLD)
#define ATTN_SMEM (4 * APLANE * 2)  // 36864 B
#define SOFTMAX_SCALE 0.1803368801f  // 0.125 * log2(e)

__global__ __launch_bounds__(256, 2)
void attn_kernel(const __half* __restrict__ qkvh, float* __restrict__ out)
{
    const int idx = blockIdx.x;        // 2048 = b(4) x h(16) x qc(32)
    const int qc = idx & 31;
    const int h  = (idx >> 5) & 15;
    const int b  = idx >> 9;
    const int q0 = qc * 128;
    const int w  = qc >> 2;

    extern __shared__ char smc[];
    const unsigned smb = (unsigned)__cvta_generic_to_shared(smc);

    const int tid = threadIdx.x;
    const int wid = tid >> 5;
    const int lane = tid & 31;
    const size_t headbase = ((size_t)(b * NHEAD + h)) * SEQ * HDIM;

    const __half* qg = qkvh + headbase + (size_t)q0 * HDIM;
    const __half* kg = qkvh + QKV_PLANE + headbase;
    const __half* vg = qkvh + 2 * QKV_PLANE + headbase;

#pragma unroll
    for (int p = 0; p < 4; p++) {
        int c = tid + p * 256;
        int r = c >> 3, col = (c & 7) * 8;
        cp16s(smb + (r * AQLD + col) * 2, qg + (size_t)r * HDIM + col);
    }
    asm volatile("cp.async.commit_group;\n");
    asm volatile("cp.async.wait_group 0;\n" ::: "memory");
    __syncthreads();

    unsigned qf[4][4];
    {
        unsigned qaddr = smb +
            (((unsigned)(wid * 16 + (lane & 7) + ((lane >> 3) & 1) * 8)) * AQLD
             + (lane >> 4) * 8) * 2;
#pragma unroll
        for (int kt = 0; kt < 4; kt++)
            ldsm4(qf[kt], qaddr + kt * 16 * 2);
    }
    __syncthreads();

    float o[8][4];
#pragma unroll
    for (int nt = 0; nt < 8; nt++) { o[nt][0] = o[nt][1] = o[nt][2] = o[nt][3] = 0.f; }
    float m0 = -1e30f, m1 = -1e30f, l0 = 0.f, l1 = 0.f;

    const int kstart = (w == 0) ? 0 : (w - 1) * WIN;
    const int kend   = q0 + 128;
    const int nch    = (kend - kstart) >> 6;

    const unsigned kaoff = (((unsigned)(lane & 7)) * AQLD + (lane >> 3) * 8) * 2;
    const unsigned vaoff = ((((unsigned)(lane & 7)) + ((lane >> 3) & 1) * 8) * AQLD
                            + (lane >> 4) * 8) * 2;
    const int rbase = q0 + wid * 16;

    auto load_kv = [&](int st, int kc) {
#pragma unroll
        for (int p = 0; p < 4; p++) {
            int c = tid + p * 256;
            int plane = c >> 9;
            int cc = c & 511;
            int r = cc >> 3, col = (cc & 7) * 8;
            const __half* s = (plane ? vg : kg) + (size_t)(kc + r) * HDIM + col;
            cp16s(smb + (st * 2 * APLANE + plane * APLANE + r * AQLD + col) * 2, s);
        }
        asm volatile("cp.async.commit_group;\n");
    };

    load_kv(0, kstart);

    for (int ci = 0; ci < nch; ci++) {
        const int kc = kstart + ci * 64;
        const int st = ci & 1;
        asm volatile("cp.async.wait_group 0;\n" ::: "memory");
        __syncthreads();
        if (ci + 1 < nch) load_kv(st ^ 1, kc + 64);

        const unsigned kb = smb + (st * 2 * APLANE) * 2;
        const unsigned vb = kb + APLANE * 2;

        float s[8][4];
#pragma unroll
        for (int nt = 0; nt < 8; nt++) {
            s[nt][0] = s[nt][1] = s[nt][2] = s[nt][3] = 0.f;
#pragma unroll
            for (int ktp = 0; ktp < 2; ktp++) {
                unsigned kf[4];
                ldsm4(kf, kb + (8 * nt) * AQLD * 2 + ktp * 32 * 2 + kaoff);
                mma16816(s[nt], qf[2 * ktp],     kf);
                mma16816(s[nt], qf[2 * ktp + 1], kf + 2);
            }
        }

        {
            const bool need_mask = (kc + 63 > rbase);
            const int r0g = rbase + (lane >> 2);
            const int r1g = r0g + 8;
            float mloc0 = -1e30f, mloc1 = -1e30f;
#pragma unroll
            for (int nt = 0; nt < 8; nt++) {
                int cg = kc + nt * 8 + (lane & 3) * 2;
                float x0 = s[nt][0] * SOFTMAX_SCALE;
                float x1 = s[nt][1] * SOFTMAX_SCALE;
                float x2 = s[nt][2] * SOFTMAX_SCALE;
                float x3 = s[nt][3] * SOFTMAX_SCALE;
                if (need_mask) {
                    if (cg     > r0g) x0 = -1e30f;
                    if (cg + 1 > r0g) x1 = -1e30f;
                    if (cg     > r1g) x2 = -1e30f;
                    if (cg + 1 > r1g) x3 = -1e30f;
                }
                s[nt][0] = x0; s[nt][1] = x1; s[nt][2] = x2; s[nt][3] = x3;
                mloc0 = fmaxf(mloc0, fmaxf(x0, x1));
                mloc1 = fmaxf(mloc1, fmaxf(x2, x3));
            }
            mloc0 = fmaxf(mloc0, __shfl_xor_sync(0xffffffffu, mloc0, 1));
            mloc0 = fmaxf(mloc0, __shfl_xor_sync(0xffffffffu, mloc0, 2));
            mloc1 = fmaxf(mloc1, __shfl_xor_sync(0xffffffffu, mloc1, 1));
            mloc1 = fmaxf(mloc1, __shfl_xor_sync(0xffffffffu, mloc1, 2));
            float mn0 = fmaxf(m0, mloc0);
            float mn1 = fmaxf(m1, mloc1);
            float al0 = exp2f(m0 - mn0);
            float al1 = exp2f(m1 - mn1);
            m0 = mn0; m1 = mn1;

            unsigned pf[4][4];
            float ss0 = 0.f, ss1 = 0.f;
#pragma unroll
            for (int nt = 0; nt < 8; nt++) {
                __half2 pz0 = h2exp2(__floats2half2_rn(s[nt][0] - mn0, s[nt][1] - mn0));
                __half2 pz1 = h2exp2(__floats2half2_rn(s[nt][2] - mn1, s[nt][3] - mn1));
                float2 f0 = __half22float2(pz0);
                float2 f1 = __half22float2(pz1);
                ss0 += f0.x + f0.y;
                ss1 += f1.x + f1.y;
                pf[nt >> 1][(nt & 1) * 2]     = *(unsigned*)&pz0;
                pf[nt >> 1][(nt & 1) * 2 + 1] = *(unsigned*)&pz1;
            }
            ss0 += __shfl_xor_sync(0xffffffffu, ss0, 1);
            ss0 += __shfl_xor_sync(0xffffffffu, ss0, 2);
            ss1 += __shfl_xor_sync(0xffffffffu, ss1, 1);
            ss1 += __shfl_xor_sync(0xffffffffu, ss1, 2);
            l0 = l0 * al0 + ss0;
            l1 = l1 * al1 + ss1;

#pragma unroll
            for (int nt = 0; nt < 8; nt++) {
                o[nt][0] *= al0; o[nt][1] *= al0;
                o[nt][2] *= al1; o[nt][3] *= al1;
            }

#pragma unroll
            for (int ndp = 0; ndp < 4; ndp++) {
#pragma unroll
                for (int kt = 0; kt < 4; kt++) {
                    unsigned vf[4];
                    ldsm4t(vf, vb + (kt * 16) * AQLD * 2 + (2 * ndp) * 8 * 2 + vaoff);
                    mma16816(o[2 * ndp],     pf[kt], vf);
                    mma16816(o[2 * ndp + 1], pf[kt], vf + 2);
                }
            }
        }
    }

    const float inv0 = 1.0f / l0;
    const float inv1 = 1.0f / l1;
    const int r0 = q0 + wid * 16 + (lane >> 2);
    const int r1 = r0 + 8;
    const int cbase = h * HDIM + (lane & 3) * 2;
#pragma unroll
    for (int nt = 0; nt < 8; nt++) {
        int col = cbase + nt * 8;
        float2 v0 = make_float2(o[nt][0] * inv0, o[nt][1] * inv0);
        float2 v1 = make_float2(o[nt][2] * inv1, o[nt][3] * inv1);
        *(float2*)(out + ((size_t)(b * SEQ + r0)) * DMODEL + col) = v0;
        *(float2*)(out + ((size_t)(b * SEQ + r1)) * DMODEL + col) = v1;
    }
}

// ============================================================================
// LayerNorm over D=1024. HALF=1: also emit fp16 plane (feeds GEMM).
// ============================================================================
template <int HALF>
__global__ __launch_bounds__(256)
void ln_kernel(const float* __restrict__ x, const float* __restrict__ gw,
               const float* __restrict__ bw, float* __restrict__ out,
               __half* __restrict__ oh)
{
    __shared__ float red[16];
    __shared__ float stats[2];
    const int row = blockIdx.x;
    const int tid = threadIdx.x;
    const float* xr = x + (size_t)row * DMODEL;

    float4 xv = *(const float4*)(xr + tid * 4);
    float s  = xv.x + xv.y + xv.z + xv.w;
    float s2 = xv.x * xv.x + xv.y * xv.y + xv.z * xv.z + xv.w * xv.w;
#pragma unroll
    for (int o = 16; o > 0; o >>= 1) {
        s  += __shfl_xor_sync(0xffffffffu, s, o);
        s2 += __shfl_xor_sync(0xffffffffu, s2, o);
    }
    if ((tid & 31) == 0) { red[tid >> 5] = s; red[8 + (tid >> 5)] = s2; }
    __syncthreads();
    if (tid == 0) {
        float ts = 0.f, ts2 = 0.f;
#pragma unroll
        for (int i = 0; i < 8; i++) { ts += red[i]; ts2 += red[8 + i]; }
        float mu  = ts * (1.0f / DMODEL);
        float var = ts2 * (1.0f / DMODEL) - mu * mu;
        stats[0] = mu;
        stats[1] = rsqrtf(var + 1e-5f);
    }
    __syncthreads();
    float mu = stats[0], rstd = stats[1];
    float4 gv = *(const float4*)(gw + tid * 4);
    float4 bv = *(const float4*)(bw + tid * 4);
    float4 ov;
    ov.x = (xv.x - mu) * rstd * gv.x + bv.x;
    ov.y = (xv.y - mu) * rstd * gv.y + bv.y;
    ov.z = (xv.z - mu) * rstd * gv.z + bv.z;
    ov.w = (xv.w - mu) * rstd * gv.w + bv.w;
    *(float4*)(out + (size_t)row * DMODEL + tid * 4) = ov;
    if constexpr (HALF == 1) {
        hi_store4(ov, oh + (size_t)row * DMODEL + tid * 4);
    }
}

// ============================================================================
extern "C" void kernel_launch(void* const* d_in, const int* in_sizes, int n_in,
                              void* d_out, int out_size)
{
    const float* src = (const float*)d_in[0];
    const float* wq  = (const float*)d_in[1];
    const float* bq  = (const float*)d_in[2];
    const float* wk  = (const float*)d_in[3];
    const float* bk  = (const float*)d_in[4];
    const float* wv  = (const float*)d_in[5];
    const float* bv  = (const float*)d_in[6];
    const float* w1  = (const float*)d_in[7];
    const float* b1  = (const float*)d_in[8];
    const float* w2  = (const float*)d_in[9];
    const float* b2  = (const float*)d_in[10];
    const float* g1  = (const float*)d_in[11];
    const float* be1 = (const float*)d_in[12];
    const float* g2  = (const float*)d_in[13];
    const float* be2 = (const float*)d_in[14];
    float* out = (float*)d_out;

    cudaFuncSetAttribute(gemm_h<0>, cudaFuncAttributeMaxDynamicSharedMemorySize, SPLIT_SMEM);
    cudaFuncSetAttribute(gemm_h<1>, cudaFuncAttributeMaxDynamicSharedMemorySize, SPLIT_SMEM);
    cudaFuncSetAttribute(gemm_h<2>, cudaFuncAttributeMaxDynamicSharedMemorySize, SPLIT_SMEM);
    cudaFuncSetAttribute(attn_kernel, cudaFuncAttributeMaxDynamicSharedMemorySize, ATTN_SMEM);

    float *attn, *xln, *y, *bqkv;
    __half *srch, *wqkvh, *w1h, *w2h, *xh, *hh, *qkvh;
    cudaGetSymbolAddress((void**)&attn, g_attn);
    cudaGetSymbolAddress((void**)&xln,  g_xln);
    cudaGetSymbolAddress((void**)&y,    g_y);
    cudaGetSymbolAddress((void**)&bqkv, g_bqkv);
    cudaGetSymbolAddress((void**)&srch, g_srch);
    cudaGetSymbolAddress((void**)&wqkvh, g_wqkvh);
    cudaGetSymbolAddress((void**)&w1h, g_w1h);
    cudaGetSymbolAddress((void**)&w2h, g_w2h);
    cudaGetSymbolAddress((void**)&xh,  g_xh);
    cudaGetSymbolAddress((void**)&hh,  g_hh);
    cudaGetSymbolAddress((void**)&qkvh, g_qkvh);

    // 0: fused prepass
    round_all<<<(RA_TOTAL + 255) / 256, 256>>>(src, wq, wk, wv, w1, w2, bq, bk, bv,
                                               srch, wqkvh, w1h, w2h, bqkv);

    // 1: fused QKV GEMM (N = 3072) -> q/k/v fp16 planes
    dim3 gQKV(3 * DMODEL / BN, MROWS / BM);        // (24, 128)
    gemm_h<0><<<gQKV, 256, SPLIT_SMEM>>>(srch, wqkvh, bqkv, nullptr,
                                         nullptr, qkvh, DMODEL, 3 * DMODEL);

    // 2: attention (FA2-style register-resident)
    attn_kernel<<<BATCH * NHEAD * (SEQ / 128), 256, ATTN_SMEM>>>(qkvh, attn);

    // 3: LN1 (fp32 + fp16 out)
    ln_kernel<1><<<MROWS, 256>>>(attn, g1, be1, xln, xh);

    // 4: FFN1 -> fp16 h
    dim3 gF1(DFF / BN, MROWS / BM);                // (32, 128)
    gemm_h<1><<<gF1, 256, SPLIT_SMEM>>>(xh, w1h, b1, nullptr,
                                        nullptr, hh, DMODEL, DFF);

    // 5: FFN2 (+residual)
    dim3 gF2(DMODEL / BN, MROWS / BM);             // (8, 128)
    gemm_h<2><<<gF2, 256, SPLIT_SMEM>>>(hh, w2h, b2, xln,
                                        y, nullptr, DFF, DMODEL);

    // 6: LN2 -> out
    ln_kernel<0><<<MROWS, 256>>>(y, g2, be2, out, nullptr);
}

// round 17
// speedup vs baseline: 1.0561x; 1.0561x over previous
#include <cuda_runtime.h>
#include <cuda_fp16.h>
#include <mma.h>
#include <cstdint>

using namespace nvcuda;

// Problem constants
#define BATCH  4
#define SEQ    4096
#define DMODEL 1024
#define NHEAD  16
#define HDIM   64
#define DFF    4096
#define WIN    512
#define MROWS  (BATCH*SEQ)          // 16384

// ---------------- scratch (device globals; no allocations allowed) ----------
static __device__ float g_attn[(size_t)MROWS * DMODEL];
static __device__ float g_xln [(size_t)MROWS * DMODEL];
static __device__ float g_y   [(size_t)MROWS * DMODEL];
// fp16 planes
static __device__ __align__(16) __half g_srch[(size_t)MROWS * DMODEL];
static __device__ __align__(16) __half g_wqkvh[(size_t)3 * DMODEL * DMODEL];
static __device__ __align__(16) __half g_w1h[(size_t)DFF * DMODEL];
static __device__ __align__(16) __half g_w2h[(size_t)DMODEL * DFF];
static __device__ __align__(16) __half g_xh [(size_t)MROWS * DMODEL];
static __device__ __align__(16) __half g_hh [(size_t)MROWS * DFF];
// q/k/v planes, [3][B,H,S,d]
static __device__ __align__(16) __half g_qkvh[(size_t)3 * MROWS * DMODEL];
static __device__ float g_bqkv[3 * DMODEL];

__device__ __forceinline__ void cp16(void* dst, const void* src) {
    unsigned int d = (unsigned int)__cvta_generic_to_shared(dst);
    asm volatile("cp.async.cg.shared.global [%0], [%1], 16;\n" :: "r"(d), "l"(src));
}
__device__ __forceinline__ void cp16s(unsigned dst, const void* src) {
    asm volatile("cp.async.cg.shared.global [%0], [%1], 16;\n" :: "r"(dst), "l"(src));
}

__device__ __forceinline__ void hi_store4(float4 x, __half* hp) {
    ((__half2*)hp)[0] = __floats2half2_rn(x.x, x.y);
    ((__half2*)hp)[1] = __floats2half2_rn(x.z, x.w);
}

__device__ __forceinline__ void ldsm4(unsigned* r, unsigned a) {
    asm volatile("ldmatrix.sync.aligned.m8n8.x4.shared.b16 {%0,%1,%2,%3}, [%4];"
                 : "=r"(r[0]), "=r"(r[1]), "=r"(r[2]), "=r"(r[3]) : "r"(a));
}
__device__ __forceinline__ void ldsm4t(unsigned* r, unsigned a) {
    asm volatile("ldmatrix.sync.aligned.m8n8.x4.trans.shared.b16 {%0,%1,%2,%3}, [%4];"
                 : "=r"(r[0]), "=r"(r[1]), "=r"(r[2]), "=r"(r[3]) : "r"(a));
}
__device__ __forceinline__ void mma16816(float* c, const unsigned* a, const unsigned* b) {
    asm volatile("mma.sync.aligned.m16n8k16.row.col.f32.f16.f16.f32 "
                 "{%0,%1,%2,%3}, {%4,%5,%6,%7}, {%8,%9}, {%0,%1,%2,%3};"
                 : "+f"(c[0]), "+f"(c[1]), "+f"(c[2]), "+f"(c[3])
                 : "r"(a[0]), "r"(a[1]), "r"(a[2]), "r"(a[3]), "r"(b[0]), "r"(b[1]));
}

// ============================================================================
// Fused prepass: src + weights -> fp16; bias pack fp32. float4-group indices.
// ============================================================================
#define RA_TOTAL 7078656
__global__ __launch_bounds__(256)
void round_all(const float* __restrict__ src,
               const float* __restrict__ wq, const float* __restrict__ wk,
               const float* __restrict__ wv, const float* __restrict__ w1,
               const float* __restrict__ w2, const float* __restrict__ bq,
               const float* __restrict__ bk, const float* __restrict__ bv,
               __half* __restrict__ srch, __half* __restrict__ wqkvh,
               __half* __restrict__ w1h, __half* __restrict__ w2h,
               float* __restrict__ bqkv)
{
    long long i = (long long)blockIdx.x * 256 + threadIdx.x;
    if (i >= RA_TOTAL) return;
    if (i >= 7077888) {                 // bias pack, fp32 copy
        long long j = i - 7077888;      // 0..767
        const float* in;
        float* op;
        if (j < 256)      { in = bq + j * 4;         op = bqkv + j * 4; }
        else if (j < 512) { in = bk + (j - 256) * 4; op = bqkv + 1024 + (j - 256) * 4; }
        else              { in = bv + (j - 512) * 4; op = bqkv + 2048 + (j - 512) * 4; }
        *(float4*)op = *(const float4*)in;
        return;
    }
    const float* in;
    __half* hp;
    if (i < 4194304)      { in = src + i * 4; hp = srch + i * 4; }
    else if (i < 4456448) { long long j = i - 4194304; in = wq + j * 4; hp = wqkvh + j * 4; }
    else if (i < 4718592) { long long j = i - 4456448; in = wk + j * 4; hp = wqkvh + 1048576 + j * 4; }
    else if (i < 4980736) { long long j = i - 4718592; in = wv + j * 4; hp = wqkvh + 2097152 + j * 4; }
    else if (i < 6029312) { long long j = i - 4980736; in = w1 + j * 4; hp = w1h + j * 4; }
    else                  { long long j = i - 6029312; in = w2 + j * 4; hp = w2h + j * 4; }
    hi_store4(*(const float4*)in, hp);
}

// ============================================================================
// Plain-fp16 TN GEMM, 2-stage cp.async pipeline, BK=64 (halved per-tile
// sync/loop overhead vs BK=32). Single sync per tile.
// Block 128x128, 8 warps as 4(m:32) x 2(n:64), warp tile 32x64.
//   MODE 0: +bias(packed), QKV scatter -> fp16 planes [3][B,H,S,d]
//   MODE 1: +bias, ReLU, fp16 out (FFN1)
//   MODE 2: +bias, +extra fp32 residual, fp32 out (FFN2)
// ============================================================================
#define BM 128
#define BN 128
#define BK 64
#define LDB 72                       // halfs per row (144B; 16B-aligned, conflict-free)
#define PLANE (128 * LDB)            // 9216 halfs
#define STG (2 * PLANE)              // A|W = 18432 halfs = 36864 B per stage
#define SPLIT_SMEM 73728             // 2 stages (epilogue 69632 fits inside)
#define QKV_PLANE ((size_t)MROWS * DMODEL)

template <int MODE>
__global__ __launch_bounds__(256, 2)
void gemm_h(const __half* __restrict__ Ah, const __half* __restrict__ Wh,
            const float* __restrict__ bias, const float* __restrict__ extra,
            float* __restrict__ out0, __half* __restrict__ oh,
            int K, int N)
{
    extern __shared__ __half smp[];
    const int tid = threadIdx.x;
    const int wid = tid >> 5;
    const int lane = tid & 31;
    const int wm = wid & 3;
    const int wn = wid >> 2;

    wmma::fragment<wmma::accumulator, 16, 16, 16, float> acc[2][4];
#pragma unroll
    for (int i = 0; i < 2; i++)
#pragma unroll
        for (int j = 0; j < 4; j++)
            wmma::fill_fragment(acc[i][j], 0.0f);

    const __half* Ahg = Ah + (size_t)blockIdx.y * BM * K;
    const __half* Whg = Wh + (size_t)blockIdx.x * BN * K;

    // stage: A 128x64 + W 128x64 halfs; 1024 8-half chunks per plane
    auto load_stage = [&](int s, int kt) {
        __half* st = smp + s * STG;
#pragma unroll
        for (int p = 0; p < 4; p++) {
            int c = tid + p * 256;            // 0..1023
            int r = c >> 3, col = (c & 7) * 8;
            size_t go = (size_t)r * K + kt + col;
            unsigned so = r * LDB + col;
            cp16(st + so,         Ahg + go);
            cp16(st + PLANE + so, Whg + go);
        }
        asm volatile("cp.async.commit_group;\n");
    };

    const int T = K / BK;
    load_stage(0, 0);

    for (int t = 0; t < T; t++) {
        asm volatile("cp.async.wait_group 0;\n" ::: "memory");
        __syncthreads();   // stage-t visible; all warps done with t-1
        if (t + 1 < T) load_stage((t + 1) & 1, (t + 1) * BK);

        const __half* Ahs = smp + (t & 1) * STG;
        const __half* Bhs = Ahs + PLANE;

#pragma unroll
        for (int kk = 0; kk < BK; kk += 16) {
            wmma::fragment<wmma::matrix_a, 16, 16, 16, __half, wmma::row_major> ah[2];
#pragma unroll
            for (int i = 0; i < 2; i++)
                wmma::load_matrix_sync(ah[i], Ahs + (wm * 32 + i * 16) * LDB + kk, LDB);
#pragma unroll
            for (int j = 0; j < 4; j++) {
                wmma::fragment<wmma::matrix_b, 16, 16, 16, __half, wmma::col_major> bh;
                wmma::load_matrix_sync(bh, Bhs + (wn * 64 + j * 16) * LDB + kk, LDB);
#pragma unroll
                for (int i = 0; i < 2; i++)
                    wmma::mma_sync(acc[i][j], ah[i], bh, acc[i][j]);
            }
        }
    }
    __syncthreads();   // all compute done before epilogue aliases stage smem

    float* Cw = (float*)smp + wid * (32 * 68);
#pragma unroll
    for (int i = 0; i < 2; i++)
#pragma unroll
        for (int j = 0; j < 4; j++)
            wmma::store_matrix_sync(Cw + (i * 16) * 68 + j * 16, acc[i][j], 68,
                                    wmma::mem_row_major);
    __syncwarp();

    const int m = blockIdx.y * BM + wm * 32 + lane;
    const int n0 = blockIdx.x * BN + wn * 64;
    const float* crow = Cw + lane * 68;

#pragma unroll
    for (int c4 = 0; c4 < 16; c4++) {
        int n = n0 + c4 * 4;
        float4 c = *(float4*)(crow + c4 * 4);
        float4 bb = *(const float4*)(bias + n);
        c.x += bb.x; c.y += bb.y; c.z += bb.z; c.w += bb.w;
        if constexpr (MODE == 1) {
            c.x = fmaxf(c.x, 0.f); c.y = fmaxf(c.y, 0.f);
            c.z = fmaxf(c.z, 0.f); c.w = fmaxf(c.w, 0.f);
            hi_store4(c, oh + (size_t)m * N + n);
        } else if constexpr (MODE == 2) {
            float4 e = *(const float4*)(extra + (size_t)m * N + n);
            c.x += e.x; c.y += e.y; c.z += e.z; c.w += e.w;
            *(float4*)(out0 + (size_t)m * N + n) = c;
        } else {
            int mat = n >> 10;
            int nl  = n & 1023;
            int h   = nl >> 6;
            int dd  = nl & (HDIM - 1);
            int bi  = m >> 12;
            int s   = m & (SEQ - 1);
            size_t o = (((size_t)bi * NHEAD + h) * SEQ + s) * HDIM + dd;
            hi_store4(c, oh + mat * QKV_PLANE + o);
        }
    }
}

// ============================================================================
// FlashAttention-2 style register-resident attention (unchanged from R15).
// ============================================================================
#define AQLD 72
#define APLANE (64 * AQLD)
#define ATTN_SMEM (4 * APLANE * 2)  // 36864 B
#define SOFTMAX_SCALE 0.1803368801f  // 0.125 * log2(e)

__global__ __launch_bounds__(256, 2)
void attn_kernel(const __half* __restrict__ qkvh, float* __restrict__ out)
{
    const int idx = blockIdx.x;        // 2048 = b(4) x h(16) x qc(32)
    const int qc = idx & 31;
    const int h  = (idx >> 5) & 15;
    const int b  = idx >> 9;
    const int q0 = qc * 128;
    const int w  = qc >> 2;

    extern __shared__ char smc[];
    const unsigned smb = (unsigned)__cvta_generic_to_shared(smc);

    const int tid = threadIdx.x;
    const int wid = tid >> 5;
    const int lane = tid & 31;
    const size_t headbase = ((size_t)(b * NHEAD + h)) * SEQ * HDIM;

    const __half* qg = qkvh + headbase + (size_t)q0 * HDIM;
    const __half* kg = qkvh + QKV_PLANE + headbase;
    const __half* vg = qkvh + 2 * QKV_PLANE + headbase;

#pragma unroll
    for (int p = 0; p < 4; p++) {
        int c = tid + p * 256;
        int r = c >> 3, col = (c & 7) * 8;
        cp16s(smb + (r * AQLD + col) * 2, qg + (size_t)r * HDIM + col);
    }
    asm volatile("cp.async.commit_group;\n");
    asm volatile("cp.async.wait_group 0;\n" ::: "memory");
    __syncthreads();

    unsigned qf[4][4];
    {
        unsigned qaddr = smb +
            (((unsigned)(wid * 16 + (lane & 7) + ((lane >> 3) & 1) * 8)) * AQLD
             + (lane >> 4) * 8) * 2;
#pragma unroll
        for (int kt = 0; kt < 4; kt++)
            ldsm4(qf[kt], qaddr + kt * 16 * 2);
    }
    __syncthreads();

    float o[8][4];
#pragma unroll
    for (int nt = 0; nt < 8; nt++) { o[nt][0] = o[nt][1] = o[nt][2] = o[nt][3] = 0.f; }
    float m0 = -1e30f, m1 = -1e30f, l0 = 0.f, l1 = 0.f;

    const int kstart = (w == 0) ? 0 : (w - 1) * WIN;
    const int kend   = q0 + 128;
    const int nch    = (kend - kstart) >> 6;

    const unsigned kaoff = (((unsigned)(lane & 7)) * AQLD + (lane >> 3) * 8) * 2;
    const unsigned vaoff = ((((unsigned)(lane & 7)) + ((lane >> 3) & 1) * 8) * AQLD
                            + (lane >> 4) * 8) * 2;
    const int rbase = q0 + wid * 16;

    auto load_kv = [&](int st, int kc) {
#pragma unroll
        for (int p = 0; p < 4; p++) {
            int c = tid + p * 256;
            int plane = c >> 9;
            int cc = c & 511;
            int r = cc >> 3, col = (cc & 7) * 8;
            const __half* s = (plane ? vg : kg) + (size_t)(kc + r) * HDIM + col;
            cp16s(smb + (st * 2 * APLANE + plane * APLANE + r * AQLD + col) * 2, s);
        }
        asm volatile("cp.async.commit_group;\n");
    };

    load_kv(0, kstart);

    for (int ci = 0; ci < nch; ci++) {
        const int kc = kstart + ci * 64;
        const int st = ci & 1;
        asm volatile("cp.async.wait_group 0;\n" ::: "memory");
        __syncthreads();
        if (ci + 1 < nch) load_kv(st ^ 1, kc + 64);

        const unsigned kb = smb + (st * 2 * APLANE) * 2;
        const unsigned vb = kb + APLANE * 2;

        float s[8][4];
#pragma unroll
        for (int nt = 0; nt < 8; nt++) {
            s[nt][0] = s[nt][1] = s[nt][2] = s[nt][3] = 0.f;
#pragma unroll
            for (int ktp = 0; ktp < 2; ktp++) {
                unsigned kf[4];
                ldsm4(kf, kb + (8 * nt) * AQLD * 2 + ktp * 32 * 2 + kaoff);
                mma16816(s[nt], qf[2 * ktp],     kf);
                mma16816(s[nt], qf[2 * ktp + 1], kf + 2);
            }
        }

        {
            const bool need_mask = (kc + 63 > rbase);
            const int r0g = rbase + (lane >> 2);
            const int r1g = r0g + 8;
            float mloc0 = -1e30f, mloc1 = -1e30f;
#pragma unroll
            for (int nt = 0; nt < 8; nt++) {
                int cg = kc + nt * 8 + (lane & 3) * 2;
                float x0 = s[nt][0] * SOFTMAX_SCALE;
                float x1 = s[nt][1] * SOFTMAX_SCALE;
                float x2 = s[nt][2] * SOFTMAX_SCALE;
                float x3 = s[nt][3] * SOFTMAX_SCALE;
                if (need_mask) {
                    if (cg     > r0g) x0 = -1e30f;
                    if (cg + 1 > r0g) x1 = -1e30f;
                    if (cg     > r1g) x2 = -1e30f;
                    if (cg + 1 > r1g) x3 = -1e30f;
                }
                s[nt][0] = x0; s[nt][1] = x1; s[nt][2] = x2; s[nt][3] = x3;
                mloc0 = fmaxf(mloc0, fmaxf(x0, x1));
                mloc1 = fmaxf(mloc1, fmaxf(x2, x3));
            }
            mloc0 = fmaxf(mloc0, __shfl_xor_sync(0xffffffffu, mloc0, 1));
            mloc0 = fmaxf(mloc0, __shfl_xor_sync(0xffffffffu, mloc0, 2));
            mloc1 = fmaxf(mloc1, __shfl_xor_sync(0xffffffffu, mloc1, 1));
            mloc1 = fmaxf(mloc1, __shfl_xor_sync(0xffffffffu, mloc1, 2));
            float mn0 = fmaxf(m0, mloc0);
            float mn1 = fmaxf(m1, mloc1);
            float al0 = exp2f(m0 - mn0);
            float al1 = exp2f(m1 - mn1);
            m0 = mn0; m1 = mn1;

            unsigned pf[4][4];
            float ss0 = 0.f, ss1 = 0.f;
#pragma unroll
            for (int nt = 0; nt < 8; nt++) {
                __half2 pz0 = h2exp2(__floats2half2_rn(s[nt][0] - mn0, s[nt][1] - mn0));
                __half2 pz1 = h2exp2(__floats2half2_rn(s[nt][2] - mn1, s[nt][3] - mn1));
                float2 f0 = __half22float2(pz0);
                float2 f1 = __half22float2(pz1);
                ss0 += f0.x + f0.y;
                ss1 += f1.x + f1.y;
                pf[nt >> 1][(nt & 1) * 2]     = *(unsigned*)&pz0;
                pf[nt >> 1][(nt & 1) * 2 + 1] = *(unsigned*)&pz1;
            }
            ss0 += __shfl_xor_sync(0xffffffffu, ss0, 1);
            ss0 += __shfl_xor_sync(0xffffffffu, ss0, 2);
            ss1 += __shfl_xor_sync(0xffffffffu, ss1, 1);
            ss1 += __shfl_xor_sync(0xffffffffu, ss1, 2);
            l0 = l0 * al0 + ss0;
            l1 = l1 * al1 + ss1;

#pragma unroll
            for (int nt = 0; nt < 8; nt++) {
                o[nt][0] *= al0; o[nt][1] *= al0;
                o[nt][2] *= al1; o[nt][3] *= al1;
            }

#pragma unroll
            for (int ndp = 0; ndp < 4; ndp++) {
#pragma unroll
                for (int kt = 0; kt < 4; kt++) {
                    unsigned vf[4];
                    ldsm4t(vf, vb + (kt * 16) * AQLD * 2 + (2 * ndp) * 8 * 2 + vaoff);
                    mma16816(o[2 * ndp],     pf[kt], vf);
                    mma16816(o[2 * ndp + 1], pf[kt], vf + 2);
                }
            }
        }
    }

    const float inv0 = 1.0f / l0;
    const float inv1 = 1.0f / l1;
    const int r0 = q0 + wid * 16 + (lane >> 2);
    const int r1 = r0 + 8;
    const int cbase = h * HDIM + (lane & 3) * 2;
#pragma unroll
    for (int nt = 0; nt < 8; nt++) {
        int col = cbase + nt * 8;
        float2 v0 = make_float2(o[nt][0] * inv0, o[nt][1] * inv0);
        float2 v1 = make_float2(o[nt][2] * inv1, o[nt][3] * inv1);
        *(float2*)(out + ((size_t)(b * SEQ + r0)) * DMODEL + col) = v0;
        *(float2*)(out + ((size_t)(b * SEQ + r1)) * DMODEL + col) = v1;
    }
}

// ============================================================================
// LayerNorm over D=1024. HALF=1: also emit fp16 plane (feeds GEMM).
// ============================================================================
template <int HALF>
__global__ __launch_bounds__(256)
void ln_kernel(const float* __restrict__ x, const float* __restrict__ gw,
               const float* __restrict__ bw, float* __restrict__ out,
               __half* __restrict__ oh)
{
    __shared__ float red[16];
    __shared__ float stats[2];
    const int row = blockIdx.x;
    const int tid = threadIdx.x;
    const float* xr = x + (size_t)row * DMODEL;

    float4 xv = *(const float4*)(xr + tid * 4);
    float s  = xv.x + xv.y + xv.z + xv.w;
    float s2 = xv.x * xv.x + xv.y * xv.y + xv.z * xv.z + xv.w * xv.w;
#pragma unroll
    for (int o = 16; o > 0; o >>= 1) {
        s  += __shfl_xor_sync(0xffffffffu, s, o);
        s2 += __shfl_xor_sync(0xffffffffu, s2, o);
    }
    if ((tid & 31) == 0) { red[tid >> 5] = s; red[8 + (tid >> 5)] = s2; }
    __syncthreads();
    if (tid == 0) {
        float ts = 0.f, ts2 = 0.f;
#pragma unroll
        for (int i = 0; i < 8; i++) { ts += red[i]; ts2 += red[8 + i]; }
        float mu  = ts * (1.0f / DMODEL);
        float var = ts2 * (1.0f / DMODEL) - mu * mu;
        stats[0] = mu;
        stats[1] = rsqrtf(var + 1e-5f);
    }
    __syncthreads();
    float mu = stats[0], rstd = stats[1];
    float4 gv = *(const float4*)(gw + tid * 4);
    float4 bv = *(const float4*)(bw + tid * 4);
    float4 ov;
    ov.x = (xv.x - mu) * rstd * gv.x + bv.x;
    ov.y = (xv.y - mu) * rstd * gv.y + bv.y;
    ov.z = (xv.z - mu) * rstd * gv.z + bv.z;
    ov.w = (xv.w - mu) * rstd * gv.w + bv.w;
    *(float4*)(out + (size_t)row * DMODEL + tid * 4) = ov;
    if constexpr (HALF == 1) {
        hi_store4(ov, oh + (size_t)row * DMODEL + tid * 4);
    }
}

// ============================================================================
extern "C" void kernel_launch(void* const* d_in, const int* in_sizes, int n_in,
                              void* d_out, int out_size)
{
    const float* src = (const float*)d_in[0];
    const float* wq  = (const float*)d_in[1];
    const float* bq  = (const float*)d_in[2];
    const float* wk  = (const float*)d_in[3];
    const float* bk  = (const float*)d_in[4];
    const float* wv  = (const float*)d_in[5];
    const float* bv  = (const float*)d_in[6];
    const float* w1  = (const float*)d_in[7];
    const float* b1  = (const float*)d_in[8];
    const float* w2  = (const float*)d_in[9];
    const float* b2  = (const float*)d_in[10];
    const float* g1  = (const float*)d_in[11];
    const float* be1 = (const float*)d_in[12];
    const float* g2  = (const float*)d_in[13];
    const float* be2 = (const float*)d_in[14];
    float* out = (float*)d_out;

    cudaFuncSetAttribute(gemm_h<0>, cudaFuncAttributeMaxDynamicSharedMemorySize, SPLIT_SMEM);
    cudaFuncSetAttribute(gemm_h<1>, cudaFuncAttributeMaxDynamicSharedMemorySize, SPLIT_SMEM);
    cudaFuncSetAttribute(gemm_h<2>, cudaFuncAttributeMaxDynamicSharedMemorySize, SPLIT_SMEM);
    cudaFuncSetAttribute(attn_kernel, cudaFuncAttributeMaxDynamicSharedMemorySize, ATTN_SMEM);

    float *attn, *xln, *y, *bqkv;
    __half *srch, *wqkvh, *w1h, *w2h, *xh, *hh, *qkvh;
    cudaGetSymbolAddress((void**)&attn, g_attn);
    cudaGetSymbolAddress((void**)&xln,  g_xln);
    cudaGetSymbolAddress((void**)&y,    g_y);
    cudaGetSymbolAddress((void**)&bqkv, g_bqkv);
    cudaGetSymbolAddress((void**)&srch, g_srch);
    cudaGetSymbolAddress((void**)&wqkvh, g_wqkvh);
    cudaGetSymbolAddress((void**)&w1h, g_w1h);
    cudaGetSymbolAddress((void**)&w2h, g_w2h);
    cudaGetSymbolAddress((void**)&xh,  g_xh);
    cudaGetSymbolAddress((void**)&hh,  g_hh);
    cudaGetSymbolAddress((void**)&qkvh, g_qkvh);

    // 0: fused prepass
    round_all<<<(RA_TOTAL + 255) / 256, 256>>>(src, wq, wk, wv, w1, w2, bq, bk, bv,
                                               srch, wqkvh, w1h, w2h, bqkv);

    // 1: fused QKV GEMM (N = 3072) -> q/k/v fp16 planes
    dim3 gQKV(3 * DMODEL / BN, MROWS / BM);        // (24, 128)
    gemm_h<0><<<gQKV, 256, SPLIT_SMEM>>>(srch, wqkvh, bqkv, nullptr,
                                         nullptr, qkvh, DMODEL, 3 * DMODEL);

    // 2: attention (FA2-style register-resident)
    attn_kernel<<<BATCH * NHEAD * (SEQ / 128), 256, ATTN_SMEM>>>(qkvh, attn);

    // 3: LN1 (fp32 + fp16 out)
    ln_kernel<1><<<MROWS, 256>>>(attn, g1, be1, xln, xh);

    // 4: FFN1 -> fp16 h
    dim3 gF1(DFF / BN, MROWS / BM);                // (32, 128)
    gemm_h<1><<<gF1, 256, SPLIT_SMEM>>>(xh, w1h, b1, nullptr,
                                        nullptr, hh, DMODEL, DFF);

    // 5: FFN2 (+residual)
    dim3 gF2(DMODEL / BN, MROWS / BM);             // (8, 128)
    gemm_h<2><<<gF2, 256, SPLIT_SMEM>>>(hh, w2h, b2, xln,
                                        y, nullptr, DFF, DMODEL);

    // 6: LN2 -> out
    ln_kernel<0><<<MROWS, 256>>>(y, g2, be2, out, nullptr);
}